// round 14
// baseline (speedup 1.0000x reference)
#include <cuda_runtime.h>
#include <cuda_fp16.h>
#include <cstdint>

#define ALPHA 0.2f
#define NT 512

// Pre-converted fp16 node weights in tail-SMEM layout (u32 = f16x2, row stride 132 u32)
static __device__ uint4 g_w1h[208 * 132 / 4];   // 195x256 valid, zero-padded
static __device__ uint4 g_w2h[256 * 132 / 4];

__device__ __forceinline__ float lrelu(float v) { return v > 0.0f ? v : ALPHA * v; }

#define FFMA2(acc, a, b) \
    asm("fma.rn.f32x2 %0, %1, %2, %0;" : "+l"(acc) : "l"(a), "l"(b))
__device__ __forceinline__ float2 unpack2(unsigned long long v) {
    float2 r;
    asm("mov.b64 {%0, %1}, %2;" : "=f"(r.x), "=f"(r.y) : "l"(v));
    return r;
}
__device__ __forceinline__ unsigned long long pack2(float lo, float hi) {
    unsigned long long r;
    asm("mov.b64 %0, {%1, %2};" : "=l"(r) : "f"(lo), "f"(hi));
    return r;
}
__device__ __forceinline__ uint32_t cvt_f16x2(float hi, float lo) {
    uint32_t d;
    asm("cvt.rn.f16x2.f32 %0, %1, %2;" : "=r"(d) : "f"(hi), "f"(lo));
    return d;
}
__device__ __forceinline__ uint32_t smem_u32(const void* p) {
    uint32_t a;
    asm("{ .reg .u64 t; cvta.to.shared.u64 t, %1; cvt.u32.u64 %0, t; }"
        : "=r"(a) : "l"(p));
    return a;
}

#define LDSM_X4(a0, a1, a2, a3, addr) \
    asm volatile("ldmatrix.sync.aligned.m8n8.x4.shared.b16 {%0,%1,%2,%3}, [%4];" \
                 : "=r"(a0), "=r"(a1), "=r"(a2), "=r"(a3) : "r"(addr))
#define LDSM_X2T(b0, b1, addr) \
    asm volatile("ldmatrix.sync.aligned.m8n8.x2.trans.shared.b16 {%0,%1}, [%2];" \
                 : "=r"(b0), "=r"(b1) : "r"(addr))
#define MMA16816(c, a0, a1, a2, a3, b0, b1) \
    asm volatile("mma.sync.aligned.m16n8k16.row.col.f32.f16.f16.f32 " \
                 "{%0,%1,%2,%3}, {%4,%5,%6,%7}, {%8,%9}, {%0,%1,%2,%3};" \
                 : "+f"((c)[0]), "+f"((c)[1]), "+f"((c)[2]), "+f"((c)[3]) \
                 : "r"(a0), "r"(a1), "r"(a2), "r"(a3), "r"(b0), "r"(b1))

// ================= PREP KERNEL =================
__global__ void __launch_bounds__(256)
prep_kernel(const float* __restrict__ w1, const float* __restrict__ w2)
{
    int i = blockIdx.x * 256 + threadIdx.x;
    if (i < 208 * 132) {
        int k = i / 132, u = i - k * 132;
        uint32_t v = 0u;
        if (k < 195 && u < 128)
            v = cvt_f16x2(w1[(size_t)k * 256 + 2 * u + 1], w1[(size_t)k * 256 + 2 * u]);
        ((uint32_t*)g_w1h)[i] = v;
    }
    if (i < 256 * 132) {
        int k = i / 132, u = i - k * 132;
        uint32_t v = 0u;
        if (u < 128)
            v = cvt_f16x2(w2[(size_t)k * 256 + 2 * u + 1], w2[(size_t)k * 256 + 2 * u]);
        ((uint32_t*)g_w2h)[i] = v;
    }
}

// ================= FUSED EDGE + NODE KERNEL (512 threads) =================
#define BW2 0
#define BW3 32256
#define BH1 96256
#define BH2 112896
#define OF_W1 34944
#define OF_B2 35616
#define OF_B3 35776
#define OF_UI 35968
#define OF_XJ 36064
#define OF_D  36292
#define BYT  145472
#define YTU  (BYT / 4)
#define BH1T 180032
#define H1TU (BH1T / 4)
#define OT_B1 34944
#define OT_B2 35200
#define OT_W3 35456
#define OT_B3 36224
#define SMEM1_BYTES 222272
#define H1B32 (BH1 / 4)
#define H2B32 (BH2 / 4)

__global__ void __launch_bounds__(NT, 1)
edge_kernel(const float* __restrict__ x,
            const float* __restrict__ w1, const float* __restrict__ b1,
            const float* __restrict__ w2, const float* __restrict__ b2,
            const float* __restrict__ w3, const float* __restrict__ b3,
            const float* __restrict__ nb1, const float* __restrict__ nb2,
            const float* __restrict__ nw3, const float* __restrict__ nb3,
            float* __restrict__ out)
{
    extern __shared__ float s[];
    uint32_t* s32 = (uint32_t*)s;
    __half* sh = (__half*)s;
    const int tid = threadIdx.x;
    const int wid = tid >> 5;       // 0..15
    const int lane = tid & 31;
    const uint32_t sbase = smem_u32(s);

    // ---- one-time init ----
    for (int i = tid; i < 672; i += NT) s[OF_W1 + i] = w1[i];
    for (int i = tid; i < 160; i += NT) s[OF_B2 + i] = b2[i];
    for (int i = tid; i < 192; i += NT) s[OF_B3 + i] = b3[i];
    for (int idx = tid; idx < 96 * 160; idx += NT) {
        int k = idx / 160, n = idx - k * 160;
        sh[k * 168 + n] = __float2half(w2[idx]);
    }
    for (int idx = tid; idx < 160 * 192; idx += NT) {
        int k = idx / 192, n = idx - k * 192;
        sh[BW3 / 2 + k * 200 + n] = __float2half(w3[idx]);
    }
    for (int idx = tid; idx < 5 * 52; idx += NT)
        s32[H1B32 + (75 + idx / 52) * 52 + (idx % 52)] = 0u;
    for (int idx = tid; idx < 80 * 108; idx += NT) s32[YTU + idx] = 0u;
    __syncthreads();

    // n-tile mapping for 16 warps: tiles {8w, 8w+128}
    const int nt1 = (wid < 4) ? 2 : 1;    // MMA1: n=160 -> 20 tiles
    const int nt2 = (wid < 8) ? 2 : 1;    // MMA2: n=192 -> 24 tiles
    int nn[2];
    nn[0] = 8 * wid; nn[1] = 8 * wid + 128;
    const int lA = lane & 15, gA = lane >> 4;
    const int lB = lane & 15;
    const int qr = lane >> 2, qc = lane & 3;
    const uint32_t a1base = sbase + BH1 + (uint32_t)(lA * 104 + gA * 8) * 2;
    const uint32_t a2base = sbase + BH2 + (uint32_t)(lA * 168 + gA * 8) * 2;
    const uint32_t b2base = sbase + BW2 + (uint32_t)(lB * 168) * 2;
    const uint32_t b3base = sbase + BW3 + (uint32_t)(lB * 200) * 2;
    float e1b0[2], e1b1[2], e2b0[2], e2b1[2];
    #pragma unroll
    for (int j = 0; j < 2; j++) {
        if (j < nt1) {
            e1b0[j] = s[OF_B2 + nn[j] + 2 * qc];
            e1b1[j] = s[OF_B2 + nn[j] + 2 * qc + 1];
        } else { e1b0[j] = 0.f; e1b1[j] = 0.f; }
        if (j < nt2) {
            e2b0[j] = s[OF_B3 + nn[j] + 2 * qc];
            e2b1[j] = s[OF_B3 + nn[j] + 2 * qc + 1];
        } else { e2b0[j] = 0.f; e2b1[j] = 0.f; }
    }

    // ================= EDGE LOOP =================
    int slot = 0;
    for (int bi = blockIdx.x; bi < 9600; bi += 148, slot++) {
        const int b = bi / 75, i = bi % 75;
        const float* xb = x + b * 75 * 3;
        const float xi0 = xb[i * 3 + 0], xi1 = xb[i * 3 + 1], xi2 = xb[i * 3 + 2];

        if (tid < 75) {
            float a0 = xb[tid * 3 + 0], a1 = xb[tid * 3 + 1], a2 = xb[tid * 3 + 2];
            s[OF_XJ + 3 * tid + 0] = a0;
            s[OF_XJ + 3 * tid + 1] = a1;
            s[OF_XJ + 3 * tid + 2] = a2;
            float d0 = (a0 - xi0) + 1e-12f;
            float d1 = (a1 - xi1) + 1e-12f;
            float d2 = (a2 - xi2) + 1e-12f;
            s[OF_D + tid] = sqrtf(d0 * d0 + d1 * d1 + d2 * d2);
        }
        if (tid < 3)
            sh[BYT / 2 + slot * 216 + 192 + tid] = __float2half(xb[i * 3 + tid]);
        if (tid >= 160 && tid < 256) {
            int c = tid - 160;
            s[OF_UI + c] = b1[c] + xi0 * s[OF_W1 + c]
                                 + xi1 * s[OF_W1 + 96 + c]
                                 + xi2 * s[OF_W1 + 192 + c];
        }
        __syncthreads();

        for (int idx = tid; idx < 75 * 48; idx += NT) {
            int r = idx / 48, w = idx - r * 48;
            float xj0 = s[OF_XJ + 3 * r + 0];
            float xj1 = s[OF_XJ + 3 * r + 1];
            float xj2 = s[OF_XJ + 3 * r + 2];
            float dj  = s[OF_D + r];
            unsigned long long v = *(const unsigned long long*)(s + OF_UI + 2 * w);
            FFMA2(v, pack2(xj0, xj0), *(const unsigned long long*)(s + OF_W1 + 288 + 2 * w));
            FFMA2(v, pack2(xj1, xj1), *(const unsigned long long*)(s + OF_W1 + 384 + 2 * w));
            FFMA2(v, pack2(xj2, xj2), *(const unsigned long long*)(s + OF_W1 + 480 + 2 * w));
            FFMA2(v, pack2(dj, dj),   *(const unsigned long long*)(s + OF_W1 + 576 + 2 * w));
            float2 vf = unpack2(v);
            s32[H1B32 + r * 52 + w] = cvt_f16x2(lrelu(vf.y), lrelu(vf.x));
        }
        __syncthreads();

        // ---- MMA1: h2 = lrelu(h1 @ W2 + b2) ----
        {
            float acc[5][2][4];
            #pragma unroll
            for (int m = 0; m < 5; m++)
                #pragma unroll
                for (int j = 0; j < 2; j++)
                    { acc[m][j][0]=0.f; acc[m][j][1]=0.f; acc[m][j][2]=0.f; acc[m][j][3]=0.f; }
            #pragma unroll
            for (int k = 0; k < 6; k++) {
                uint32_t bf[2][2];
                #pragma unroll
                for (int j = 0; j < 2; j++)
                    if (j < nt1) { LDSM_X2T(bf[j][0], bf[j][1], b2base + k * 5376 + nn[j] * 2); }
                #pragma unroll
                for (int m = 0; m < 5; m++) {
                    uint32_t a0, a1, a2, a3;
                    LDSM_X4(a0, a1, a2, a3, a1base + m * 3328 + k * 32);
                    #pragma unroll
                    for (int j = 0; j < 2; j++)
                        if (j < nt1) MMA16816(acc[m][j], a0, a1, a2, a3, bf[j][0], bf[j][1]);
                }
            }
            #pragma unroll
            for (int m = 0; m < 5; m++) {
                int r1 = m * 16 + qr, r2 = r1 + 8;
                #pragma unroll
                for (int j = 0; j < 2; j++)
                    if (j < nt1) {
                        uint32_t u = nn[j] / 2 + qc;
                        s32[H2B32 + r1 * 84 + u] =
                            cvt_f16x2(lrelu(acc[m][j][1] + e1b1[j]),
                                      lrelu(acc[m][j][0] + e1b0[j]));
                        s32[H2B32 + r2 * 84 + u] =
                            cvt_f16x2(lrelu(acc[m][j][3] + e1b1[j]),
                                      lrelu(acc[m][j][2] + e1b0[j]));
                    }
            }
        }
        __syncthreads();

        // ---- MMA2: column sums of lrelu(h2 @ W3 + b3) -> y tile ----
        {
            float acc[5][2][4];
            #pragma unroll
            for (int m = 0; m < 5; m++)
                #pragma unroll
                for (int j = 0; j < 2; j++)
                    { acc[m][j][0]=0.f; acc[m][j][1]=0.f; acc[m][j][2]=0.f; acc[m][j][3]=0.f; }
            #pragma unroll
            for (int k = 0; k < 10; k++) {
                uint32_t bf[2][2];
                #pragma unroll
                for (int j = 0; j < 2; j++)
                    if (j < nt2) { LDSM_X2T(bf[j][0], bf[j][1], b3base + k * 6400 + nn[j] * 2); }
                #pragma unroll
                for (int m = 0; m < 5; m++) {
                    uint32_t a0, a1, a2, a3;
                    LDSM_X4(a0, a1, a2, a3, a2base + m * 5376 + k * 32);
                    #pragma unroll
                    for (int j = 0; j < 2; j++)
                        if (j < nt2) MMA16816(acc[m][j], a0, a1, a2, a3, bf[j][0], bf[j][1]);
                }
            }
            float cs0[2] = {0.f, 0.f}, cs1[2] = {0.f, 0.f};
            #pragma unroll
            for (int m = 0; m < 5; m++) {
                bool ok2 = (m * 16 + 8 + qr) < 75;
                #pragma unroll
                for (int j = 0; j < 2; j++) {
                    cs0[j] += lrelu(acc[m][j][0] + e2b0[j]);
                    cs1[j] += lrelu(acc[m][j][1] + e2b1[j]);
                    if (ok2) {
                        cs0[j] += lrelu(acc[m][j][2] + e2b0[j]);
                        cs1[j] += lrelu(acc[m][j][3] + e2b1[j]);
                    }
                }
            }
            #pragma unroll
            for (int j = 0; j < 2; j++) {
                #pragma unroll
                for (int d = 4; d < 32; d <<= 1) {
                    cs0[j] += __shfl_xor_sync(0xFFFFFFFFu, cs0[j], d);
                    cs1[j] += __shfl_xor_sync(0xFFFFFFFFu, cs1[j], d);
                }
            }
            if (lane < 4) {
                #pragma unroll
                for (int j = 0; j < 2; j++)
                    if (j < nt2)
                        s32[YTU + slot * 108 + nn[j] / 2 + lane] = cvt_f16x2(cs1[j], cs0[j]);
            }
        }
        __syncthreads();
    }

    // ================= NODE TAIL =================
    const int nslots = (blockIdx.x < 128) ? 65 : 64;
    const int n0 = 16 * wid;                    // 16 cols (2 tiles) per warp
    const uint32_t aYbase  = sbase + BYT  + (uint32_t)(lA * 216 + gA * 8) * 2;
    const uint32_t aH1base = sbase + BH1T + (uint32_t)(lA * 264 + gA * 8) * 2;
    const uint32_t bWbase  = sbase + (uint32_t)(lB * 264) * 2;

    for (int i = tid; i < 256; i += NT) s[OT_B1 + i] = nb1[i];
    for (int i = tid; i < 256; i += NT) s[OT_B2 + i] = nb2[i];
    for (int i = tid; i < 768; i += NT) s[OT_W3 + i] = nw3[i];
    if (tid < 3) s[OT_B3 + tid] = nb3[tid];
    {
        uint4* d = (uint4*)s32;
        for (int i = tid; i < 208 * 132 / 4; i += NT) d[i] = g_w1h[i];
    }
    __syncthreads();

    // ---- Tail phase 1: h1[80][256] = lrelu(y @ W1 + b1), K=208 ----
    {
        float acc[5][2][4];
        #pragma unroll
        for (int m = 0; m < 5; m++)
            #pragma unroll
            for (int j = 0; j < 2; j++)
                { acc[m][j][0]=0.f; acc[m][j][1]=0.f; acc[m][j][2]=0.f; acc[m][j][3]=0.f; }
        #pragma unroll
        for (int kc = 0; kc < 13; kc++) {
            uint32_t bf[2][2];
            #pragma unroll
            for (int j = 0; j < 2; j++)
                LDSM_X2T(bf[j][0], bf[j][1], bWbase + kc * 8448 + (n0 + 8 * j) * 2);
            #pragma unroll
            for (int m = 0; m < 5; m++) {
                uint32_t a0, a1, a2, a3;
                LDSM_X4(a0, a1, a2, a3, aYbase + m * 6912 + kc * 32);
                #pragma unroll
                for (int j = 0; j < 2; j++)
                    MMA16816(acc[m][j], a0, a1, a2, a3, bf[j][0], bf[j][1]);
            }
        }
        #pragma unroll
        for (int m = 0; m < 5; m++) {
            int r1 = m * 16 + qr, r2 = r1 + 8;
            #pragma unroll
            for (int j = 0; j < 2; j++) {
                float bb0 = s[OT_B1 + n0 + 8 * j + 2 * qc];
                float bb1 = s[OT_B1 + n0 + 8 * j + 2 * qc + 1];
                uint32_t u = n0 / 2 + 4 * j + qc;
                s32[H1TU + r1 * 132 + u] =
                    cvt_f16x2(lrelu(acc[m][j][1] + bb1), lrelu(acc[m][j][0] + bb0));
                s32[H1TU + r2 * 132 + u] =
                    cvt_f16x2(lrelu(acc[m][j][3] + bb1), lrelu(acc[m][j][2] + bb0));
            }
        }
    }
    __syncthreads();

    {
        uint4* d = (uint4*)s32;
        for (int i = tid; i < 256 * 132 / 4; i += NT) d[i] = g_w2h[i];
    }
    __syncthreads();

    // ---- Tail phase 2: h2 = lrelu(h1 @ W2 + b2), K=256; park h2 in W region ----
    {
        float acc[5][2][4];
        #pragma unroll
        for (int m = 0; m < 5; m++)
            #pragma unroll
            for (int j = 0; j < 2; j++)
                { acc[m][j][0]=0.f; acc[m][j][1]=0.f; acc[m][j][2]=0.f; acc[m][j][3]=0.f; }
        #pragma unroll
        for (int kc = 0; kc < 16; kc++) {
            uint32_t bf[2][2];
            #pragma unroll
            for (int j = 0; j < 2; j++)
                LDSM_X2T(bf[j][0], bf[j][1], bWbase + kc * 8448 + (n0 + 8 * j) * 2);
            #pragma unroll
            for (int m = 0; m < 5; m++) {
                uint32_t a0, a1, a2, a3;
                LDSM_X4(a0, a1, a2, a3, aH1base + m * 8448 + kc * 32);
                #pragma unroll
                for (int j = 0; j < 2; j++)
                    MMA16816(acc[m][j], a0, a1, a2, a3, bf[j][0], bf[j][1]);
            }
        }
        __syncthreads();   // all W2 reads done before overwriting W region with h2
        #pragma unroll
        for (int m = 0; m < 5; m++) {
            int r1 = m * 16 + qr, r2 = r1 + 8;
            #pragma unroll
            for (int j = 0; j < 2; j++) {
                float bb0 = s[OT_B2 + n0 + 8 * j + 2 * qc];
                float bb1 = s[OT_B2 + n0 + 8 * j + 2 * qc + 1];
                uint32_t u = n0 / 2 + 4 * j + qc;
                s32[r1 * 132 + u] =
                    cvt_f16x2(lrelu(acc[m][j][1] + bb1), lrelu(acc[m][j][0] + bb0));
                s32[r2 * 132 + u] =
                    cvt_f16x2(lrelu(acc[m][j][3] + bb1), lrelu(acc[m][j][2] + bb0));
            }
        }
    }
    __syncthreads();

    // ---- Tail phase 3: out[slot][3] = h2 @ W3 + b3 ----
    if (tid < 240) {
        int r = tid / 3, o = tid - r * 3;
        if (r < nslots) {
            const __half2* hr = (const __half2*)(sh + r * 264);
            float a = s[OT_B3 + o];
            #pragma unroll 8
            for (int k2 = 0; k2 < 128; k2++) {
                float2 h = __half22float2(hr[k2]);
                a += h.x * s[OT_W3 + 6 * k2 + o] + h.y * s[OT_W3 + 6 * k2 + 3 + o];
            }
            out[(blockIdx.x + r * 148) * 3 + o] = a;
        }
    }
}

extern "C" void kernel_launch(void* const* d_in, const int* in_sizes, int n_in,
                              void* d_out, int out_size)
{
    const float* x    = (const float*)d_in[0];
    const float* few1 = (const float*)d_in[1];
    const float* feb1 = (const float*)d_in[2];
    const float* few2 = (const float*)d_in[3];
    const float* feb2 = (const float*)d_in[4];
    const float* few3 = (const float*)d_in[5];
    const float* feb3 = (const float*)d_in[6];
    const float* fnw1 = (const float*)d_in[7];
    const float* fnb1 = (const float*)d_in[8];
    const float* fnw2 = (const float*)d_in[9];
    const float* fnb2 = (const float*)d_in[10];
    const float* fnw3 = (const float*)d_in[11];
    const float* fnb3 = (const float*)d_in[12];
    float* out = (float*)d_out;

    cudaFuncSetAttribute(edge_kernel, cudaFuncAttributeMaxDynamicSharedMemorySize, SMEM1_BYTES);

    prep_kernel<<<132, 256>>>(fnw1, fnw2);
    edge_kernel<<<148, NT, SMEM1_BYTES>>>(x, few1, feb1, few2, feb2, few3, feb3,
                                          fnb1, fnb2, fnw3, fnb3, out);
}

// round 15
// speedup vs baseline: 1.9365x; 1.9365x over previous
#include <cuda_runtime.h>
#include <cuda_fp16.h>
#include <cstdint>

#define ALPHA 0.2f

// Pre-converted fp16 node weights in tail-SMEM layout (u32 = f16x2, row stride 132 u32)
static __device__ uint4 g_w1h[208 * 132 / 4];   // 195x256 valid, zero-padded
static __device__ uint4 g_w2h[256 * 132 / 4];

__device__ __forceinline__ float lrelu(float v) { return v > 0.0f ? v : ALPHA * v; }

#define FFMA2(acc, a, b) \
    asm("fma.rn.f32x2 %0, %1, %2, %0;" : "+l"(acc) : "l"(a), "l"(b))
__device__ __forceinline__ float2 unpack2(unsigned long long v) {
    float2 r;
    asm("mov.b64 {%0, %1}, %2;" : "=f"(r.x), "=f"(r.y) : "l"(v));
    return r;
}
__device__ __forceinline__ unsigned long long pack2(float lo, float hi) {
    unsigned long long r;
    asm("mov.b64 %0, {%1, %2};" : "=l"(r) : "f"(lo), "f"(hi));
    return r;
}
__device__ __forceinline__ uint32_t cvt_f16x2(float hi, float lo) {
    uint32_t d;
    asm("cvt.rn.f16x2.f32 %0, %1, %2;" : "=r"(d) : "f"(hi), "f"(lo));
    return d;
}
__device__ __forceinline__ uint32_t smem_u32(const void* p) {
    uint32_t a;
    asm("{ .reg .u64 t; cvta.to.shared.u64 t, %1; cvt.u32.u64 %0, t; }"
        : "=r"(a) : "l"(p));
    return a;
}

#define LDSM_X4(a0, a1, a2, a3, addr) \
    asm volatile("ldmatrix.sync.aligned.m8n8.x4.shared.b16 {%0,%1,%2,%3}, [%4];" \
                 : "=r"(a0), "=r"(a1), "=r"(a2), "=r"(a3) : "r"(addr))
#define LDSM_X2T(b0, b1, addr) \
    asm volatile("ldmatrix.sync.aligned.m8n8.x2.trans.shared.b16 {%0,%1}, [%2];" \
                 : "=r"(b0), "=r"(b1) : "r"(addr))
// stmatrix: lane<16 provides row addr; all lanes provide data in MMA C-frag layout
#define STSM_X2(addr, r0, r1) \
    asm volatile("stmatrix.sync.aligned.m8n8.x2.shared.b16 [%0], {%1, %2};" \
                 :: "r"(addr), "r"(r0), "r"(r1) : "memory")
#define MMA16816(c, a0, a1, a2, a3, b0, b1) \
    asm volatile("mma.sync.aligned.m16n8k16.row.col.f32.f16.f16.f32 " \
                 "{%0,%1,%2,%3}, {%4,%5,%6,%7}, {%8,%9}, {%0,%1,%2,%3};" \
                 : "+f"((c)[0]), "+f"((c)[1]), "+f"((c)[2]), "+f"((c)[3]) \
                 : "r"(a0), "r"(a1), "r"(a2), "r"(a3), "r"(b0), "r"(b1))

// ================= PREP KERNEL =================
__global__ void __launch_bounds__(256)
prep_kernel(const float* __restrict__ w1, const float* __restrict__ w2)
{
    int i = blockIdx.x * 256 + threadIdx.x;
    if (i < 208 * 132) {
        int k = i / 132, u = i - k * 132;
        uint32_t v = 0u;
        if (k < 195 && u < 128)
            v = cvt_f16x2(w1[(size_t)k * 256 + 2 * u + 1], w1[(size_t)k * 256 + 2 * u]);
        ((uint32_t*)g_w1h)[i] = v;
    }
    if (i < 256 * 132) {
        int k = i / 132, u = i - k * 132;
        uint32_t v = 0u;
        if (u < 128)
            v = cvt_f16x2(w2[(size_t)k * 256 + 2 * u + 1], w2[(size_t)k * 256 + 2 * u]);
        ((uint32_t*)g_w2h)[i] = v;
    }
}

// ================= FUSED EDGE + NODE KERNEL (R13 + stmatrix epilogues) =================
#define BW2 0
#define BW3 32256
#define BH1 96256
#define BH2 112896
#define OF_W1 34944
#define OF_B2 35616
#define OF_B3 35776
#define OF_UI 35968
#define OF_XJ 36064
#define OF_D  36292
#define BYT  145472
#define YTU  (BYT / 4)
#define BH1T 180032
#define H1TU (BH1T / 4)
#define OT_B1 34944
#define OT_B2 35200
#define OT_W3 35456
#define OT_B3 36224
#define SMEM1_BYTES 222272
#define H1B32 (BH1 / 4)
#define H2B32 (BH2 / 4)

__global__ void __launch_bounds__(256, 1)
edge_kernel(const float* __restrict__ x,
            const float* __restrict__ w1, const float* __restrict__ b1,
            const float* __restrict__ w2, const float* __restrict__ b2,
            const float* __restrict__ w3, const float* __restrict__ b3,
            const float* __restrict__ nb1, const float* __restrict__ nb2,
            const float* __restrict__ nw3, const float* __restrict__ nb3,
            float* __restrict__ out)
{
    extern __shared__ float s[];
    uint32_t* s32 = (uint32_t*)s;
    __half* sh = (__half*)s;
    const int tid = threadIdx.x;
    const int wid = tid >> 5;
    const int lane = tid & 31;
    const uint32_t sbase = smem_u32(s);

    // ---- one-time init ----
    for (int i = tid; i < 672; i += 256) s[OF_W1 + i] = w1[i];
    for (int i = tid; i < 160; i += 256) s[OF_B2 + i] = b2[i];
    for (int i = tid; i < 192; i += 256) s[OF_B3 + i] = b3[i];
    for (int idx = tid; idx < 96 * 160; idx += 256) {
        int k = idx / 160, n = idx - k * 160;
        sh[k * 168 + n] = __float2half(w2[idx]);
    }
    for (int idx = tid; idx < 160 * 192; idx += 256) {
        int k = idx / 192, n = idx - k * 192;
        sh[BW3 / 2 + k * 200 + n] = __float2half(w3[idx]);
    }
    for (int idx = tid; idx < 5 * 52; idx += 256)
        s32[H1B32 + (75 + idx / 52) * 52 + (idx % 52)] = 0u;
    for (int idx = tid; idx < 80 * 108; idx += 256) s32[YTU + idx] = 0u;
    __syncthreads();

    const int nt1 = (wid < 4) ? 3 : 2;
    int n1[3], n2[3];
    #pragma unroll
    for (int j = 0; j < 3; j++) { n1[j] = 8 * wid + 64 * j; n2[j] = 8 * wid + 64 * j; }
    const int lA = lane & 15, gA = lane >> 4;
    const int lB = lane & 15;
    const int qr = lane >> 2, qc = lane & 3;
    const uint32_t a1base = sbase + BH1 + (uint32_t)(lA * 104 + gA * 8) * 2;
    const uint32_t a2base = sbase + BH2 + (uint32_t)(lA * 168 + gA * 8) * 2;
    const uint32_t b2base = sbase + BW2 + (uint32_t)(lB * 168) * 2;
    const uint32_t b3base = sbase + BW3 + (uint32_t)(lB * 200) * 2;
    // stmatrix row base for h2 tile: row (lane&15), stride 336 B
    const uint32_t h2stb = sbase + BH2 + (uint32_t)(lane & 15) * 336;
    float e1b0[3], e1b1[3], e2b0[3], e2b1[3];
    #pragma unroll
    for (int j = 0; j < 3; j++) {
        if (j < nt1) {
            e1b0[j] = s[OF_B2 + n1[j] + 2 * qc];
            e1b1[j] = s[OF_B2 + n1[j] + 2 * qc + 1];
        } else { e1b0[j] = 0.f; e1b1[j] = 0.f; }
        e2b0[j] = s[OF_B3 + n2[j] + 2 * qc];
        e2b1[j] = s[OF_B3 + n2[j] + 2 * qc + 1];
    }

    // ---- hoist loop-invariant B fragments ----
    uint32_t bf2[6][3][2];
    uint32_t bf3[10][3][2];
    #pragma unroll
    for (int k = 0; k < 6; k++)
        #pragma unroll
        for (int j = 0; j < 3; j++) {
            if (j < nt1) { LDSM_X2T(bf2[k][j][0], bf2[k][j][1], b2base + k * 5376 + n1[j] * 2); }
            else { bf2[k][j][0] = 0u; bf2[k][j][1] = 0u; }
        }
    #pragma unroll
    for (int k = 0; k < 10; k++)
        #pragma unroll
        for (int j = 0; j < 3; j++)
            LDSM_X2T(bf3[k][j][0], bf3[k][j][1], b3base + k * 6400 + n2[j] * 2);

    // ================= EDGE LOOP =================
    int slot = 0;
    for (int bi = blockIdx.x; bi < 9600; bi += 148, slot++) {
        const int b = bi / 75, i = bi % 75;
        const float* xb = x + b * 75 * 3;
        const float xi0 = xb[i * 3 + 0], xi1 = xb[i * 3 + 1], xi2 = xb[i * 3 + 2];

        if (tid < 75) {
            float a0 = xb[tid * 3 + 0], a1 = xb[tid * 3 + 1], a2 = xb[tid * 3 + 2];
            s[OF_XJ + 3 * tid + 0] = a0;
            s[OF_XJ + 3 * tid + 1] = a1;
            s[OF_XJ + 3 * tid + 2] = a2;
            float d0 = (a0 - xi0) + 1e-12f;
            float d1 = (a1 - xi1) + 1e-12f;
            float d2 = (a2 - xi2) + 1e-12f;
            s[OF_D + tid] = sqrtf(d0 * d0 + d1 * d1 + d2 * d2);
        }
        if (tid < 3)
            sh[BYT / 2 + slot * 216 + 192 + tid] = __float2half(xb[i * 3 + tid]);
        if (tid >= 160) {
            int c = tid - 160;
            s[OF_UI + c] = b1[c] + xi0 * s[OF_W1 + c]
                                 + xi1 * s[OF_W1 + 96 + c]
                                 + xi2 * s[OF_W1 + 192 + c];
        }
        __syncthreads();

        for (int idx = tid; idx < 75 * 48; idx += 256) {
            int r = idx / 48, w = idx - r * 48;
            float xj0 = s[OF_XJ + 3 * r + 0];
            float xj1 = s[OF_XJ + 3 * r + 1];
            float xj2 = s[OF_XJ + 3 * r + 2];
            float dj  = s[OF_D + r];
            unsigned long long v = *(const unsigned long long*)(s + OF_UI + 2 * w);
            FFMA2(v, pack2(xj0, xj0), *(const unsigned long long*)(s + OF_W1 + 288 + 2 * w));
            FFMA2(v, pack2(xj1, xj1), *(const unsigned long long*)(s + OF_W1 + 384 + 2 * w));
            FFMA2(v, pack2(xj2, xj2), *(const unsigned long long*)(s + OF_W1 + 480 + 2 * w));
            FFMA2(v, pack2(dj, dj),   *(const unsigned long long*)(s + OF_W1 + 576 + 2 * w));
            float2 vf = unpack2(v);
            s32[H1B32 + r * 52 + w] = cvt_f16x2(lrelu(vf.y), lrelu(vf.x));
        }
        __syncthreads();

        // ---- MMA1: h2 = lrelu(h1 @ W2 + b2), stmatrix epilogue ----
        {
            float acc[5][3][4];
            #pragma unroll
            for (int m = 0; m < 5; m++)
                #pragma unroll
                for (int j = 0; j < 3; j++)
                    { acc[m][j][0]=0.f; acc[m][j][1]=0.f; acc[m][j][2]=0.f; acc[m][j][3]=0.f; }
            #pragma unroll
            for (int k = 0; k < 6; k++) {
                #pragma unroll
                for (int m = 0; m < 5; m++) {
                    uint32_t a0, a1, a2, a3;
                    LDSM_X4(a0, a1, a2, a3, a1base + m * 3328 + k * 32);
                    #pragma unroll
                    for (int j = 0; j < 3; j++)
                        if (j < nt1) MMA16816(acc[m][j], a0, a1, a2, a3, bf2[k][j][0], bf2[k][j][1]);
                }
            }
            #pragma unroll
            for (int m = 0; m < 5; m++) {
                #pragma unroll
                for (int j = 0; j < 3; j++)
                    if (j < nt1) {
                        uint32_t p0 = cvt_f16x2(lrelu(acc[m][j][1] + e1b1[j]),
                                                lrelu(acc[m][j][0] + e1b0[j]));
                        uint32_t p1 = cvt_f16x2(lrelu(acc[m][j][3] + e1b1[j]),
                                                lrelu(acc[m][j][2] + e1b0[j]));
                        STSM_X2(h2stb + (uint32_t)(m * 16) * 336 + n1[j] * 2, p0, p1);
                    }
            }
        }
        __syncthreads();

        // ---- MMA2: column sums of lrelu(h2 @ W3 + b3) -> y tile ----
        {
            float acc[5][3][4];
            #pragma unroll
            for (int m = 0; m < 5; m++)
                #pragma unroll
                for (int j = 0; j < 3; j++)
                    { acc[m][j][0]=0.f; acc[m][j][1]=0.f; acc[m][j][2]=0.f; acc[m][j][3]=0.f; }
            #pragma unroll
            for (int k = 0; k < 10; k++) {
                #pragma unroll
                for (int m = 0; m < 5; m++) {
                    uint32_t a0, a1, a2, a3;
                    LDSM_X4(a0, a1, a2, a3, a2base + m * 5376 + k * 32);
                    #pragma unroll
                    for (int j = 0; j < 3; j++)
                        MMA16816(acc[m][j], a0, a1, a2, a3, bf3[k][j][0], bf3[k][j][1]);
                }
            }
            float cs0[3] = {0.f, 0.f, 0.f}, cs1[3] = {0.f, 0.f, 0.f};
            #pragma unroll
            for (int m = 0; m < 5; m++) {
                bool ok2 = (m * 16 + 8 + qr) < 75;
                #pragma unroll
                for (int j = 0; j < 3; j++) {
                    cs0[j] += lrelu(acc[m][j][0] + e2b0[j]);
                    cs1[j] += lrelu(acc[m][j][1] + e2b1[j]);
                    if (ok2) {
                        cs0[j] += lrelu(acc[m][j][2] + e2b0[j]);
                        cs1[j] += lrelu(acc[m][j][3] + e2b1[j]);
                    }
                }
            }
            #pragma unroll
            for (int j = 0; j < 3; j++) {
                #pragma unroll
                for (int d = 4; d < 32; d <<= 1) {
                    cs0[j] += __shfl_xor_sync(0xFFFFFFFFu, cs0[j], d);
                    cs1[j] += __shfl_xor_sync(0xFFFFFFFFu, cs1[j], d);
                }
            }
            if (lane < 4) {
                #pragma unroll
                for (int j = 0; j < 3; j++)
                    s32[YTU + slot * 108 + n2[j] / 2 + lane] = cvt_f16x2(cs1[j], cs0[j]);
            }
        }
        __syncthreads();
    }

    // ================= NODE TAIL =================
    const int nslots = (blockIdx.x < 128) ? 65 : 64;
    const int n0 = 32 * wid;
    const uint32_t aYbase  = sbase + BYT  + (uint32_t)(lA * 216 + gA * 8) * 2;
    const uint32_t aH1base = sbase + BH1T + (uint32_t)(lA * 264 + gA * 8) * 2;
    const uint32_t bWbase  = sbase + (uint32_t)(lB * 264) * 2;
    const uint32_t h1tstb  = sbase + BH1T + (uint32_t)(lane & 15) * 528;
    const uint32_t h2tstb  = sbase + (uint32_t)(lane & 15) * 528;

    for (int i = tid; i < 256; i += 256) s[OT_B1 + i] = nb1[i];
    for (int i = tid; i < 256; i += 256) s[OT_B2 + i] = nb2[i];
    for (int i = tid; i < 768; i += 256) s[OT_W3 + i] = nw3[i];
    if (tid < 3) s[OT_B3 + tid] = nb3[tid];
    {
        uint4* d = (uint4*)s32;
        for (int i = tid; i < 208 * 132 / 4; i += 256) d[i] = g_w1h[i];
    }
    __syncthreads();

    // ---- Tail phase 1: h1[80][256] = lrelu(y @ W1 + b1), K=208 ----
    {
        float acc[5][4][4];
        #pragma unroll
        for (int m = 0; m < 5; m++)
            #pragma unroll
            for (int j = 0; j < 4; j++)
                { acc[m][j][0]=0.f; acc[m][j][1]=0.f; acc[m][j][2]=0.f; acc[m][j][3]=0.f; }
        #pragma unroll
        for (int kc = 0; kc < 13; kc++) {
            uint32_t bf[4][2];
            #pragma unroll
            for (int j = 0; j < 4; j++)
                LDSM_X2T(bf[j][0], bf[j][1], bWbase + kc * 8448 + (n0 + 8 * j) * 2);
            #pragma unroll
            for (int m = 0; m < 5; m++) {
                uint32_t a0, a1, a2, a3;
                LDSM_X4(a0, a1, a2, a3, aYbase + m * 6912 + kc * 32);
                #pragma unroll
                for (int j = 0; j < 4; j++)
                    MMA16816(acc[m][j], a0, a1, a2, a3, bf[j][0], bf[j][1]);
            }
        }
        #pragma unroll
        for (int m = 0; m < 5; m++) {
            #pragma unroll
            for (int j = 0; j < 4; j++) {
                float bb0 = s[OT_B1 + n0 + 8 * j + 2 * qc];
                float bb1 = s[OT_B1 + n0 + 8 * j + 2 * qc + 1];
                uint32_t p0 = cvt_f16x2(lrelu(acc[m][j][1] + bb1), lrelu(acc[m][j][0] + bb0));
                uint32_t p1 = cvt_f16x2(lrelu(acc[m][j][3] + bb1), lrelu(acc[m][j][2] + bb0));
                STSM_X2(h1tstb + (uint32_t)(m * 16) * 528 + (n0 + 8 * j) * 2, p0, p1);
            }
        }
    }
    __syncthreads();

    {
        uint4* d = (uint4*)s32;
        for (int i = tid; i < 256 * 132 / 4; i += 256) d[i] = g_w2h[i];
    }
    __syncthreads();

    // ---- Tail phase 2: h2 = lrelu(h1 @ W2 + b2), K=256; park h2 in W region ----
    {
        float acc[5][4][4];
        #pragma unroll
        for (int m = 0; m < 5; m++)
            #pragma unroll
            for (int j = 0; j < 4; j++)
                { acc[m][j][0]=0.f; acc[m][j][1]=0.f; acc[m][j][2]=0.f; acc[m][j][3]=0.f; }
        #pragma unroll
        for (int kc = 0; kc < 16; kc++) {
            uint32_t bf[4][2];
            #pragma unroll
            for (int j = 0; j < 4; j++)
                LDSM_X2T(bf[j][0], bf[j][1], bWbase + kc * 8448 + (n0 + 8 * j) * 2);
            #pragma unroll
            for (int m = 0; m < 5; m++) {
                uint32_t a0, a1, a2, a3;
                LDSM_X4(a0, a1, a2, a3, aH1base + m * 8448 + kc * 32);
                #pragma unroll
                for (int j = 0; j < 4; j++)
                    MMA16816(acc[m][j], a0, a1, a2, a3, bf[j][0], bf[j][1]);
            }
        }
        __syncthreads();   // all W2 reads done before overwriting W region with h2
        #pragma unroll
        for (int m = 0; m < 5; m++) {
            #pragma unroll
            for (int j = 0; j < 4; j++) {
                float bb0 = s[OT_B2 + n0 + 8 * j + 2 * qc];
                float bb1 = s[OT_B2 + n0 + 8 * j + 2 * qc + 1];
                uint32_t p0 = cvt_f16x2(lrelu(acc[m][j][1] + bb1), lrelu(acc[m][j][0] + bb0));
                uint32_t p1 = cvt_f16x2(lrelu(acc[m][j][3] + bb1), lrelu(acc[m][j][2] + bb0));
                STSM_X2(h2tstb + (uint32_t)(m * 16) * 528 + (n0 + 8 * j) * 2, p0, p1);
            }
        }
    }
    __syncthreads();

    // ---- Tail phase 3: out[slot][3] = h2 @ W3 + b3 ----
    if (tid < 240) {
        int r = tid / 3, o = tid - r * 3;
        if (r < nslots) {
            const __half2* hr = (const __half2*)(sh + r * 264);
            float a = s[OT_B3 + o];
            #pragma unroll 8
            for (int k2 = 0; k2 < 128; k2++) {
                float2 h = __half22float2(hr[k2]);
                a += h.x * s[OT_W3 + 6 * k2 + o] + h.y * s[OT_W3 + 6 * k2 + 3 + o];
            }
            out[(blockIdx.x + r * 148) * 3 + o] = a;
        }
    }
}

extern "C" void kernel_launch(void* const* d_in, const int* in_sizes, int n_in,
                              void* d_out, int out_size)
{
    const float* x    = (const float*)d_in[0];
    const float* few1 = (const float*)d_in[1];
    const float* feb1 = (const float*)d_in[2];
    const float* few2 = (const float*)d_in[3];
    const float* feb2 = (const float*)d_in[4];
    const float* few3 = (const float*)d_in[5];
    const float* feb3 = (const float*)d_in[6];
    const float* fnw1 = (const float*)d_in[7];
    const float* fnb1 = (const float*)d_in[8];
    const float* fnw2 = (const float*)d_in[9];
    const float* fnb2 = (const float*)d_in[10];
    const float* fnw3 = (const float*)d_in[11];
    const float* fnb3 = (const float*)d_in[12];
    float* out = (float*)d_out;

    cudaFuncSetAttribute(edge_kernel, cudaFuncAttributeMaxDynamicSharedMemorySize, SMEM1_BYTES);

    prep_kernel<<<132, 256>>>(fnw1, fnw2);
    edge_kernel<<<148, 256, SMEM1_BYTES>>>(x, few1, feb1, few2, feb2, few3, feb3,
                                           fnb1, fnb2, fnw3, fnb3, out);
}

// round 16
// speedup vs baseline: 2.3263x; 1.2012x over previous
#include <cuda_runtime.h>
#include <cuda_fp16.h>
#include <cstdint>

#define ALPHA 0.2f

// Pre-converted fp16 node weights in tail-SMEM layout (u32 = f16x2, row stride 132 u32)
static __device__ uint4 g_w1h[208 * 132 / 4];   // 195x256 valid, zero-padded
static __device__ uint4 g_w2h[256 * 132 / 4];

__device__ __forceinline__ float lrelu(float v) { return v > 0.0f ? v : ALPHA * v; }

__device__ __forceinline__ uint32_t cvt_f16x2(float hi, float lo) {
    uint32_t d;
    asm("cvt.rn.f16x2.f32 %0, %1, %2;" : "=r"(d) : "f"(hi), "f"(lo));
    return d;
}
__device__ __forceinline__ uint32_t smem_u32(const void* p) {
    uint32_t a;
    asm("{ .reg .u64 t; cvta.to.shared.u64 t, %1; cvt.u32.u64 %0, t; }"
        : "=r"(a) : "l"(p));
    return a;
}

#define LDSM_X4(a0, a1, a2, a3, addr) \
    asm volatile("ldmatrix.sync.aligned.m8n8.x4.shared.b16 {%0,%1,%2,%3}, [%4];" \
                 : "=r"(a0), "=r"(a1), "=r"(a2), "=r"(a3) : "r"(addr))
#define LDSM_X2T(b0, b1, addr) \
    asm volatile("ldmatrix.sync.aligned.m8n8.x2.trans.shared.b16 {%0,%1}, [%2];" \
                 : "=r"(b0), "=r"(b1) : "r"(addr))
#define STSM_X2(addr, r0, r1) \
    asm volatile("stmatrix.sync.aligned.m8n8.x2.shared.b16 [%0], {%1, %2};" \
                 :: "r"(addr), "r"(r0), "r"(r1) : "memory")
#define MMA16816(c, a0, a1, a2, a3, b0, b1) \
    asm volatile("mma.sync.aligned.m16n8k16.row.col.f32.f16.f16.f32 " \
                 "{%0,%1,%2,%3}, {%4,%5,%6,%7}, {%8,%9}, {%0,%1,%2,%3};" \
                 : "+f"((c)[0]), "+f"((c)[1]), "+f"((c)[2]), "+f"((c)[3]) \
                 : "r"(a0), "r"(a1), "r"(a2), "r"(a3), "r"(b0), "r"(b1))

// ================= PREP KERNEL =================
__global__ void __launch_bounds__(256)
prep_kernel(const float* __restrict__ w1, const float* __restrict__ w2)
{
    int i = blockIdx.x * 256 + threadIdx.x;
    if (i < 208 * 132) {
        int k = i / 132, u = i - k * 132;
        uint32_t v = 0u;
        if (k < 195 && u < 128)
            v = cvt_f16x2(w1[(size_t)k * 256 + 2 * u + 1], w1[(size_t)k * 256 + 2 * u]);
        ((uint32_t*)g_w1h)[i] = v;
    }
    if (i < 256 * 132) {
        int k = i / 132, u = i - k * 132;
        uint32_t v = 0u;
        if (u < 128)
            v = cvt_f16x2(w2[(size_t)k * 256 + 2 * u + 1], w2[(size_t)k * 256 + 2 * u]);
        ((uint32_t*)g_w2h)[i] = v;
    }
}

// ================= FUSED EDGE + NODE KERNEL =================
#define BW2 0
#define BW3 32256
#define BH1 96256      // h1 fp16 [80 m][104 halfs stride] (also W1_aug staging at init)
#define BH2 112896
#define BAUG 139776    // A_aug fp16 [80 m][16 halfs] = 2560 B
#define OF_B2 35616    // float idx
#define OF_B3 35776
#define BYT  145472
#define YTU  (BYT / 4)
#define BH1T 180032
#define H1TU (BH1T / 4)
#define OT_B1 34944
#define OT_B2 35200
#define OT_W3 35456
#define OT_B3 36224
#define SMEM1_BYTES 222272
#define H1B32 (BH1 / 4)
#define H2B32 (BH2 / 4)

__global__ void __launch_bounds__(256, 1)
edge_kernel(const float* __restrict__ x,
            const float* __restrict__ w1, const float* __restrict__ b1,
            const float* __restrict__ w2, const float* __restrict__ b2,
            const float* __restrict__ w3, const float* __restrict__ b3,
            const float* __restrict__ nb1, const float* __restrict__ nb2,
            const float* __restrict__ nw3, const float* __restrict__ nb3,
            float* __restrict__ out)
{
    extern __shared__ float s[];
    uint32_t* s32 = (uint32_t*)s;
    __half* sh = (__half*)s;
    char* sbytes = (char*)s;
    const int tid = threadIdx.x;
    const int wid = tid >> 5;
    const int lane = tid & 31;
    const uint32_t sbase = smem_u32(s);

    // ---- init phase I: biases, W2/W3 fp16, zeros ----
    for (int i = tid; i < 160; i += 256) s[OF_B2 + i] = b2[i];
    for (int i = tid; i < 192; i += 256) s[OF_B3 + i] = b3[i];
    for (int idx = tid; idx < 96 * 160; idx += 256) {
        int k = idx / 160, n = idx - k * 160;
        sh[k * 168 + n] = __float2half(w2[idx]);
    }
    for (int idx = tid; idx < 160 * 192; idx += 256) {
        int k = idx / 192, n = idx - k * 192;
        sh[BW3 / 2 + k * 200 + n] = __float2half(w3[idx]);
    }
    for (int idx = tid; idx < 5 * 52; idx += 256)
        s32[H1B32 + (75 + idx / 52) * 52 + (idx % 52)] = 0u;      // h1 pad rows
    for (int idx = tid; idx < 80 * 108; idx += 256) s32[YTU + idx] = 0u;   // y tile
    for (int idx = tid; idx < 16 * 52; idx += 256) s32[H1B32 + idx] = 0u;  // W1_aug staging
    // A_aug: zero col-halves 8-15 (all 80 rows) and full pad rows 75-79
    for (int idx = tid; idx < 80 * 4; idx += 256)
        ((uint32_t*)(sbytes + BAUG))[idx * 2 + (idx & 3) - (idx & 3) + 0] = 0u;  // placeholder (rewritten below)
    __syncthreads();
    // proper A_aug zeroing (whole region once; per-bi only first 16B/row rewritten)
    for (int idx = tid; idx < 80 * 8; idx += 256)
        ((uint32_t*)(sbytes + BAUG))[idx] = 0u;
    // init phase II: fill W1_aug rows 0-6 = w1, row 7 = b1  (staged in BH1 region)
    __syncthreads();
    for (int idx = tid; idx < 7 * 96; idx += 256) {
        int k = idx / 96, n = idx - k * 96;
        sh[BH1 / 2 + k * 104 + n] = __float2half(w1[idx]);
    }
    for (int i = tid; i < 96; i += 256) sh[BH1 / 2 + 7 * 104 + i] = __float2half(b1[i]);
    __syncthreads();

    // ---- per-warp constants ----
    const int nt1 = (wid < 4) ? 3 : 2;
    const int nt0 = (wid < 4) ? 2 : 1;
    int n1[3], n2[3], naug[2];
    #pragma unroll
    for (int j = 0; j < 3; j++) { n1[j] = 8 * wid + 64 * j; n2[j] = 8 * wid + 64 * j; }
    naug[0] = 8 * wid; naug[1] = 64 + 8 * wid;
    const int lA = lane & 15, gA = lane >> 4;
    const int lB = lane & 15;
    const int qr = lane >> 2, qc = lane & 3;
    const uint32_t a1base = sbase + BH1 + (uint32_t)(lA * 104 + gA * 8) * 2;
    const uint32_t a2base = sbase + BH2 + (uint32_t)(lA * 168 + gA * 8) * 2;
    const uint32_t aAugb  = sbase + BAUG + (uint32_t)(lA * 32 + gA * 16);
    const uint32_t b2base = sbase + BW2 + (uint32_t)(lB * 168) * 2;
    const uint32_t b3base = sbase + BW3 + (uint32_t)(lB * 200) * 2;
    const uint32_t h1stb = sbase + BH1 + (uint32_t)(lane & 15) * 208;
    const uint32_t h2stb = sbase + BH2 + (uint32_t)(lane & 15) * 336;
    float e1b0[3], e1b1[3], e2b0[3], e2b1[3];
    #pragma unroll
    for (int j = 0; j < 3; j++) {
        if (j < nt1) {
            e1b0[j] = s[OF_B2 + n1[j] + 2 * qc];
            e1b1[j] = s[OF_B2 + n1[j] + 2 * qc + 1];
        } else { e1b0[j] = 0.f; e1b1[j] = 0.f; }
        e2b0[j] = s[OF_B3 + n2[j] + 2 * qc];
        e2b1[j] = s[OF_B3 + n2[j] + 2 * qc + 1];
    }

    // ---- hoist loop-invariant B fragments (W1_aug, W2, W3) ----
    uint32_t bf1[2][2];
    #pragma unroll
    for (int j = 0; j < 2; j++) {
        if (j < nt0) { LDSM_X2T(bf1[j][0], bf1[j][1], sbase + BH1 + lB * 208 + naug[j] * 2); }
        else { bf1[j][0] = 0u; bf1[j][1] = 0u; }
    }
    uint32_t bf2[6][3][2];
    uint32_t bf3[10][3][2];
    #pragma unroll
    for (int k = 0; k < 6; k++)
        #pragma unroll
        for (int j = 0; j < 3; j++) {
            if (j < nt1) { LDSM_X2T(bf2[k][j][0], bf2[k][j][1], b2base + k * 5376 + n1[j] * 2); }
            else { bf2[k][j][0] = 0u; bf2[k][j][1] = 0u; }
        }
    #pragma unroll
    for (int k = 0; k < 10; k++)
        #pragma unroll
        for (int j = 0; j < 3; j++)
            LDSM_X2T(bf3[k][j][0], bf3[k][j][1], b3base + k * 6400 + n2[j] * 2);
    __syncthreads();   // staging reads done before h1 region reused

    // ================= EDGE LOOP =================
    int slot = 0;
    for (int bi = blockIdx.x; bi < 9600; bi += 148, slot++) {
        const int b = bi / 75, i = bi % 75;
        const float* xb = x + b * 75 * 3;
        const float xi0 = xb[i * 3 + 0], xi1 = xb[i * 3 + 1], xi2 = xb[i * 3 + 2];

        // ---- Phase A: build A_aug rows [xi|xj|d|1] ----
        if (tid < 75) {
            float a0 = xb[tid * 3 + 0], a1 = xb[tid * 3 + 1], a2 = xb[tid * 3 + 2];
            float d0 = (a0 - xi0) + 1e-12f;
            float d1 = (a1 - xi1) + 1e-12f;
            float d2 = (a2 - xi2) + 1e-12f;
            float dj = sqrtf(d0 * d0 + d1 * d1 + d2 * d2);
            uint4 row;
            row.x = cvt_f16x2(xi1, xi0);
            row.y = cvt_f16x2(a0, xi2);
            row.z = cvt_f16x2(a2, a1);
            row.w = cvt_f16x2(1.0f, dj);
            *(uint4*)(sbytes + BAUG + tid * 32) = row;
        }
        if (tid < 3)
            sh[BYT / 2 + slot * 216 + 192 + tid] = __float2half(xb[i * 3 + tid]);
        __syncthreads();

        // ---- MMA0: h1 = lrelu(A_aug @ W1_aug), K=16 (bias folded) ----
        {
            float acc[5][2][4];
            #pragma unroll
            for (int m = 0; m < 5; m++)
                #pragma unroll
                for (int j = 0; j < 2; j++)
                    { acc[m][j][0]=0.f; acc[m][j][1]=0.f; acc[m][j][2]=0.f; acc[m][j][3]=0.f; }
            #pragma unroll
            for (int m = 0; m < 5; m++) {
                uint32_t a0, a1, a2, a3;
                LDSM_X4(a0, a1, a2, a3, aAugb + m * 512);
                #pragma unroll
                for (int j = 0; j < 2; j++)
                    if (j < nt0) MMA16816(acc[m][j], a0, a1, a2, a3, bf1[j][0], bf1[j][1]);
            }
            #pragma unroll
            for (int m = 0; m < 5; m++) {
                #pragma unroll
                for (int j = 0; j < 2; j++)
                    if (j < nt0) {
                        uint32_t p0 = cvt_f16x2(lrelu(acc[m][j][1]), lrelu(acc[m][j][0]));
                        uint32_t p1 = cvt_f16x2(lrelu(acc[m][j][3]), lrelu(acc[m][j][2]));
                        STSM_X2(h1stb + (uint32_t)(m * 16) * 208 + naug[j] * 2, p0, p1);
                    }
            }
        }
        __syncthreads();

        // ---- MMA1: h2 = lrelu(h1 @ W2 + b2), stmatrix epilogue ----
        {
            float acc[5][3][4];
            #pragma unroll
            for (int m = 0; m < 5; m++)
                #pragma unroll
                for (int j = 0; j < 3; j++)
                    { acc[m][j][0]=0.f; acc[m][j][1]=0.f; acc[m][j][2]=0.f; acc[m][j][3]=0.f; }
            #pragma unroll
            for (int k = 0; k < 6; k++) {
                #pragma unroll
                for (int m = 0; m < 5; m++) {
                    uint32_t a0, a1, a2, a3;
                    LDSM_X4(a0, a1, a2, a3, a1base + m * 3328 + k * 32);
                    #pragma unroll
                    for (int j = 0; j < 3; j++)
                        if (j < nt1) MMA16816(acc[m][j], a0, a1, a2, a3, bf2[k][j][0], bf2[k][j][1]);
                }
            }
            #pragma unroll
            for (int m = 0; m < 5; m++) {
                #pragma unroll
                for (int j = 0; j < 3; j++)
                    if (j < nt1) {
                        uint32_t p0 = cvt_f16x2(lrelu(acc[m][j][1] + e1b1[j]),
                                                lrelu(acc[m][j][0] + e1b0[j]));
                        uint32_t p1 = cvt_f16x2(lrelu(acc[m][j][3] + e1b1[j]),
                                                lrelu(acc[m][j][2] + e1b0[j]));
                        STSM_X2(h2stb + (uint32_t)(m * 16) * 336 + n1[j] * 2, p0, p1);
                    }
            }
        }
        __syncthreads();

        // ---- MMA2: column sums of lrelu(h2 @ W3 + b3) -> y tile ----
        {
            float acc[5][3][4];
            #pragma unroll
            for (int m = 0; m < 5; m++)
                #pragma unroll
                for (int j = 0; j < 3; j++)
                    { acc[m][j][0]=0.f; acc[m][j][1]=0.f; acc[m][j][2]=0.f; acc[m][j][3]=0.f; }
            #pragma unroll
            for (int k = 0; k < 10; k++) {
                #pragma unroll
                for (int m = 0; m < 5; m++) {
                    uint32_t a0, a1, a2, a3;
                    LDSM_X4(a0, a1, a2, a3, a2base + m * 5376 + k * 32);
                    #pragma unroll
                    for (int j = 0; j < 3; j++)
                        MMA16816(acc[m][j], a0, a1, a2, a3, bf3[k][j][0], bf3[k][j][1]);
                }
            }
            float cs0[3] = {0.f, 0.f, 0.f}, cs1[3] = {0.f, 0.f, 0.f};
            #pragma unroll
            for (int m = 0; m < 5; m++) {
                bool ok2 = (m * 16 + 8 + qr) < 75;
                #pragma unroll
                for (int j = 0; j < 3; j++) {
                    cs0[j] += lrelu(acc[m][j][0] + e2b0[j]);
                    cs1[j] += lrelu(acc[m][j][1] + e2b1[j]);
                    if (ok2) {
                        cs0[j] += lrelu(acc[m][j][2] + e2b0[j]);
                        cs1[j] += lrelu(acc[m][j][3] + e2b1[j]);
                    }
                }
            }
            #pragma unroll
            for (int j = 0; j < 3; j++) {
                #pragma unroll
                for (int d = 4; d < 32; d <<= 1) {
                    cs0[j] += __shfl_xor_sync(0xFFFFFFFFu, cs0[j], d);
                    cs1[j] += __shfl_xor_sync(0xFFFFFFFFu, cs1[j], d);
                }
            }
            if (lane < 4) {
                #pragma unroll
                for (int j = 0; j < 3; j++)
                    s32[YTU + slot * 108 + n2[j] / 2 + lane] = cvt_f16x2(cs1[j], cs0[j]);
            }
        }
        __syncthreads();
    }

    // ================= NODE TAIL =================
    const int nslots = (blockIdx.x < 128) ? 65 : 64;
    const int n0 = 32 * wid;
    const uint32_t aYbase  = sbase + BYT  + (uint32_t)(lA * 216 + gA * 8) * 2;
    const uint32_t aH1base = sbase + BH1T + (uint32_t)(lA * 264 + gA * 8) * 2;
    const uint32_t bWbase  = sbase + (uint32_t)(lB * 264) * 2;
    const uint32_t h1tstb  = sbase + BH1T + (uint32_t)(lane & 15) * 528;
    const uint32_t h2tstb  = sbase + (uint32_t)(lane & 15) * 528;

    for (int i = tid; i < 256; i += 256) s[OT_B1 + i] = nb1[i];
    for (int i = tid; i < 256; i += 256) s[OT_B2 + i] = nb2[i];
    for (int i = tid; i < 768; i += 256) s[OT_W3 + i] = nw3[i];
    if (tid < 3) s[OT_B3 + tid] = nb3[tid];
    {
        uint4* d = (uint4*)s32;
        for (int i = tid; i < 208 * 132 / 4; i += 256) d[i] = g_w1h[i];
    }
    __syncthreads();

    // ---- Tail phase 1 ----
    {
        float acc[5][4][4];
        #pragma unroll
        for (int m = 0; m < 5; m++)
            #pragma unroll
            for (int j = 0; j < 4; j++)
                { acc[m][j][0]=0.f; acc[m][j][1]=0.f; acc[m][j][2]=0.f; acc[m][j][3]=0.f; }
        #pragma unroll
        for (int kc = 0; kc < 13; kc++) {
            uint32_t bf[4][2];
            #pragma unroll
            for (int j = 0; j < 4; j++)
                LDSM_X2T(bf[j][0], bf[j][1], bWbase + kc * 8448 + (n0 + 8 * j) * 2);
            #pragma unroll
            for (int m = 0; m < 5; m++) {
                uint32_t a0, a1, a2, a3;
                LDSM_X4(a0, a1, a2, a3, aYbase + m * 6912 + kc * 32);
                #pragma unroll
                for (int j = 0; j < 4; j++)
                    MMA16816(acc[m][j], a0, a1, a2, a3, bf[j][0], bf[j][1]);
            }
        }
        #pragma unroll
        for (int m = 0; m < 5; m++) {
            #pragma unroll
            for (int j = 0; j < 4; j++) {
                float bb0 = s[OT_B1 + n0 + 8 * j + 2 * qc];
                float bb1 = s[OT_B1 + n0 + 8 * j + 2 * qc + 1];
                uint32_t p0 = cvt_f16x2(lrelu(acc[m][j][1] + bb1), lrelu(acc[m][j][0] + bb0));
                uint32_t p1 = cvt_f16x2(lrelu(acc[m][j][3] + bb1), lrelu(acc[m][j][2] + bb0));
                STSM_X2(h1tstb + (uint32_t)(m * 16) * 528 + (n0 + 8 * j) * 2, p0, p1);
            }
        }
    }
    __syncthreads();

    {
        uint4* d = (uint4*)s32;
        for (int i = tid; i < 256 * 132 / 4; i += 256) d[i] = g_w2h[i];
    }
    __syncthreads();

    // ---- Tail phase 2 ----
    {
        float acc[5][4][4];
        #pragma unroll
        for (int m = 0; m < 5; m++)
            #pragma unroll
            for (int j = 0; j < 4; j++)
                { acc[m][j][0]=0.f; acc[m][j][1]=0.f; acc[m][j][2]=0.f; acc[m][j][3]=0.f; }
        #pragma unroll
        for (int kc = 0; kc < 16; kc++) {
            uint32_t bf[4][2];
            #pragma unroll
            for (int j = 0; j < 4; j++)
                LDSM_X2T(bf[j][0], bf[j][1], bWbase + kc * 8448 + (n0 + 8 * j) * 2);
            #pragma unroll
            for (int m = 0; m < 5; m++) {
                uint32_t a0, a1, a2, a3;
                LDSM_X4(a0, a1, a2, a3, aH1base + m * 8448 + kc * 32);
                #pragma unroll
                for (int j = 0; j < 4; j++)
                    MMA16816(acc[m][j], a0, a1, a2, a3, bf[j][0], bf[j][1]);
            }
        }
        __syncthreads();
        #pragma unroll
        for (int m = 0; m < 5; m++) {
            #pragma unroll
            for (int j = 0; j < 4; j++) {
                float bb0 = s[OT_B2 + n0 + 8 * j + 2 * qc];
                float bb1 = s[OT_B2 + n0 + 8 * j + 2 * qc + 1];
                uint32_t p0 = cvt_f16x2(lrelu(acc[m][j][1] + bb1), lrelu(acc[m][j][0] + bb0));
                uint32_t p1 = cvt_f16x2(lrelu(acc[m][j][3] + bb1), lrelu(acc[m][j][2] + bb0));
                STSM_X2(h2tstb + (uint32_t)(m * 16) * 528 + (n0 + 8 * j) * 2, p0, p1);
            }
        }
    }
    __syncthreads();

    // ---- Tail phase 3 ----
    if (tid < 240) {
        int r = tid / 3, o = tid - r * 3;
        if (r < nslots) {
            const __half2* hr = (const __half2*)(sh + r * 264);
            float a = s[OT_B3 + o];
            #pragma unroll 8
            for (int k2 = 0; k2 < 128; k2++) {
                float2 h = __half22float2(hr[k2]);
                a += h.x * s[OT_W3 + 6 * k2 + o] + h.y * s[OT_W3 + 6 * k2 + 3 + o];
            }
            out[(blockIdx.x + r * 148) * 3 + o] = a;
        }
    }
}

extern "C" void kernel_launch(void* const* d_in, const int* in_sizes, int n_in,
                              void* d_out, int out_size)
{
    const float* x    = (const float*)d_in[0];
    const float* few1 = (const float*)d_in[1];
    const float* feb1 = (const float*)d_in[2];
    const float* few2 = (const float*)d_in[3];
    const float* feb2 = (const float*)d_in[4];
    const float* few3 = (const float*)d_in[5];
    const float* feb3 = (const float*)d_in[6];
    const float* fnw1 = (const float*)d_in[7];
    const float* fnb1 = (const float*)d_in[8];
    const float* fnw2 = (const float*)d_in[9];
    const float* fnb2 = (const float*)d_in[10];
    const float* fnw3 = (const float*)d_in[11];
    const float* fnb3 = (const float*)d_in[12];
    float* out = (float*)d_out;

    cudaFuncSetAttribute(edge_kernel, cudaFuncAttributeMaxDynamicSharedMemorySize, SMEM1_BYTES);

    prep_kernel<<<132, 256>>>(fnw1, fnw2);
    edge_kernel<<<148, 256, SMEM1_BYTES>>>(x, few1, feb1, few2, feb2, few3, feb3,
                                           fnb1, fnb2, fnw3, fnb3, out);
}

// round 17
// speedup vs baseline: 2.3681x; 1.0180x over previous
#include <cuda_runtime.h>
#include <cuda_fp16.h>
#include <cstdint>

#define ALPHA 0.2f

// Pre-converted fp16 node weights in tail-SMEM layout (u32 = f16x2, row stride 132 u32)
static __device__ uint4 g_w1h[208 * 132 / 4];   // 195x256 valid, zero-padded
static __device__ uint4 g_w2h[256 * 132 / 4];

__device__ __forceinline__ float lrelu(float v) { return v > 0.0f ? v : ALPHA * v; }

__device__ __forceinline__ uint32_t cvt_f16x2(float hi, float lo) {
    uint32_t d;
    asm("cvt.rn.f16x2.f32 %0, %1, %2;" : "=r"(d) : "f"(hi), "f"(lo));
    return d;
}
__device__ __forceinline__ uint32_t smem_u32(const void* p) {
    uint32_t a;
    asm("{ .reg .u64 t; cvta.to.shared.u64 t, %1; cvt.u32.u64 %0, t; }"
        : "=r"(a) : "l"(p));
    return a;
}

#define LDSM_X4(a0, a1, a2, a3, addr) \
    asm volatile("ldmatrix.sync.aligned.m8n8.x4.shared.b16 {%0,%1,%2,%3}, [%4];" \
                 : "=r"(a0), "=r"(a1), "=r"(a2), "=r"(a3) : "r"(addr))
#define LDSM_X2T(b0, b1, addr) \
    asm volatile("ldmatrix.sync.aligned.m8n8.x2.trans.shared.b16 {%0,%1}, [%2];" \
                 : "=r"(b0), "=r"(b1) : "r"(addr))
#define STSM_X2(addr, r0, r1) \
    asm volatile("stmatrix.sync.aligned.m8n8.x2.shared.b16 [%0], {%1, %2};" \
                 :: "r"(addr), "r"(r0), "r"(r1) : "memory")
#define MMA16816(c, a0, a1, a2, a3, b0, b1) \
    asm volatile("mma.sync.aligned.m16n8k16.row.col.f32.f16.f16.f32 " \
                 "{%0,%1,%2,%3}, {%4,%5,%6,%7}, {%8,%9}, {%0,%1,%2,%3};" \
                 : "+f"((c)[0]), "+f"((c)[1]), "+f"((c)[2]), "+f"((c)[3]) \
                 : "r"(a0), "r"(a1), "r"(a2), "r"(a3), "r"(b0), "r"(b1))

// ================= PREP KERNEL =================
__global__ void __launch_bounds__(256)
prep_kernel(const float* __restrict__ w1, const float* __restrict__ w2)
{
    int i = blockIdx.x * 256 + threadIdx.x;
    if (i < 208 * 132) {
        int k = i / 132, u = i - k * 132;
        uint32_t v = 0u;
        if (k < 195 && u < 128)
            v = cvt_f16x2(w1[(size_t)k * 256 + 2 * u + 1], w1[(size_t)k * 256 + 2 * u]);
        ((uint32_t*)g_w1h)[i] = v;
    }
    if (i < 256 * 132) {
        int k = i / 132, u = i - k * 132;
        uint32_t v = 0u;
        if (u < 128)
            v = cvt_f16x2(w2[(size_t)k * 256 + 2 * u + 1], w2[(size_t)k * 256 + 2 * u]);
        ((uint32_t*)g_w2h)[i] = v;
    }
}

// ================= FUSED EDGE + NODE KERNEL (2-stage pipeline) =================
#define BW2 0
#define BW3 32256
#define BH1 96256      // h1 fp16 [80 m][104 halfs stride] (W1_aug staging at init)
#define BH2 112896
#define BAUG 139776    // A_aug fp16 [80 m][16 halfs] = 2560 B
#define OF_B2 35616    // float idx
#define OF_B3 35776
#define BYT  145472
#define YTU  (BYT / 4)
#define BH1T 180032
#define H1TU (BH1T / 4)
#define OT_B1 34944
#define OT_B2 35200
#define OT_W3 35456
#define OT_B3 36224
#define SMEM1_BYTES 222272
#define H1B32 (BH1 / 4)
#define H2B32 (BH2 / 4)

__global__ void __launch_bounds__(256, 1)
edge_kernel(const float* __restrict__ x,
            const float* __restrict__ w1, const float* __restrict__ b1,
            const float* __restrict__ w2, const float* __restrict__ b2,
            const float* __restrict__ w3, const float* __restrict__ b3,
            const float* __restrict__ nb1, const float* __restrict__ nb2,
            const float* __restrict__ nw3, const float* __restrict__ nb3,
            float* __restrict__ out)
{
    extern __shared__ float s[];
    uint32_t* s32 = (uint32_t*)s;
    __half* sh = (__half*)s;
    char* sbytes = (char*)s;
    const int tid = threadIdx.x;
    const int wid = tid >> 5;
    const int lane = tid & 31;
    const uint32_t sbase = smem_u32(s);

    // ---- init: biases, W2/W3 fp16, zeros ----
    for (int i = tid; i < 160; i += 256) s[OF_B2 + i] = b2[i];
    for (int i = tid; i < 192; i += 256) s[OF_B3 + i] = b3[i];
    for (int idx = tid; idx < 96 * 160; idx += 256) {
        int k = idx / 160, n = idx - k * 160;
        sh[k * 168 + n] = __float2half(w2[idx]);
    }
    for (int idx = tid; idx < 160 * 192; idx += 256) {
        int k = idx / 192, n = idx - k * 192;
        sh[BW3 / 2 + k * 200 + n] = __float2half(w3[idx]);
    }
    for (int idx = tid; idx < 5 * 52; idx += 256)
        s32[H1B32 + (75 + idx / 52) * 52 + (idx % 52)] = 0u;      // h1 pad rows
    for (int idx = tid; idx < 80 * 108; idx += 256) s32[YTU + idx] = 0u;   // y tile
    for (int idx = tid; idx < 16 * 52; idx += 256) s32[H1B32 + idx] = 0u;  // W1_aug staging
    for (int idx = tid; idx < 80 * 8; idx += 256)
        ((uint32_t*)(sbytes + BAUG))[idx] = 0u;                   // A_aug (incl pad rows)
    __syncthreads();
    // W1_aug rows 0-6 = w1, row 7 = b1 (staged in BH1 region, stride 104 halfs)
    for (int idx = tid; idx < 7 * 96; idx += 256) {
        int k = idx / 96, n = idx - k * 96;
        sh[BH1 / 2 + k * 104 + n] = __float2half(w1[idx]);
    }
    for (int i = tid; i < 96; i += 256) sh[BH1 / 2 + 7 * 104 + i] = __float2half(b1[i]);
    __syncthreads();

    // ---- per-warp constants ----
    const int nt1 = (wid < 4) ? 3 : 2;
    const int nt0 = (wid < 4) ? 2 : 1;
    int n1[3], n2[3], naug[2];
    #pragma unroll
    for (int j = 0; j < 3; j++) { n1[j] = 8 * wid + 64 * j; n2[j] = 8 * wid + 64 * j; }
    naug[0] = 8 * wid; naug[1] = 64 + 8 * wid;
    const int lA = lane & 15, gA = lane >> 4;
    const int lB = lane & 15;
    const int qr = lane >> 2, qc = lane & 3;
    const uint32_t a1base = sbase + BH1 + (uint32_t)(lA * 104 + gA * 8) * 2;
    const uint32_t a2base = sbase + BH2 + (uint32_t)(lA * 168 + gA * 8) * 2;
    const uint32_t aAugb  = sbase + BAUG + (uint32_t)(lA * 32 + gA * 16);
    const uint32_t b2base = sbase + BW2 + (uint32_t)(lB * 168) * 2;
    const uint32_t b3base = sbase + BW3 + (uint32_t)(lB * 200) * 2;
    const uint32_t h1stb = sbase + BH1 + (uint32_t)(lane & 15) * 208;
    const uint32_t h2stb = sbase + BH2 + (uint32_t)(lane & 15) * 336;
    float e1b0[3], e1b1[3], e2b0[3], e2b1[3];
    #pragma unroll
    for (int j = 0; j < 3; j++) {
        if (j < nt1) {
            e1b0[j] = s[OF_B2 + n1[j] + 2 * qc];
            e1b1[j] = s[OF_B2 + n1[j] + 2 * qc + 1];
        } else { e1b0[j] = 0.f; e1b1[j] = 0.f; }
        e2b0[j] = s[OF_B3 + n2[j] + 2 * qc];
        e2b1[j] = s[OF_B3 + n2[j] + 2 * qc + 1];
    }

    // ---- hoist loop-invariant B fragments (W1_aug, W2, W3) ----
    uint32_t bf1[2][2];
    #pragma unroll
    for (int j = 0; j < 2; j++) {
        if (j < nt0) { LDSM_X2T(bf1[j][0], bf1[j][1], sbase + BH1 + lB * 208 + naug[j] * 2); }
        else { bf1[j][0] = 0u; bf1[j][1] = 0u; }
    }
    uint32_t bf2[6][3][2];
    uint32_t bf3[10][3][2];
    #pragma unroll
    for (int k = 0; k < 6; k++)
        #pragma unroll
        for (int j = 0; j < 3; j++) {
            if (j < nt1) { LDSM_X2T(bf2[k][j][0], bf2[k][j][1], b2base + k * 5376 + n1[j] * 2); }
            else { bf2[k][j][0] = 0u; bf2[k][j][1] = 0u; }
        }
    #pragma unroll
    for (int k = 0; k < 10; k++)
        #pragma unroll
        for (int j = 0; j < 3; j++)
            LDSM_X2T(bf3[k][j][0], bf3[k][j][1], b3base + k * 6400 + n2[j] * 2);
    __syncthreads();   // staging reads done before h1 region reused

    // ---- pipeline stage bodies ----
    auto phaseA = [&](int bi2, int slot2) {
        const int b2i = bi2 / 75, i2 = bi2 - b2i * 75;
        const float* xb2 = x + b2i * 225;
        if (tid < 75) {
            float xi0 = xb2[i2 * 3], xi1 = xb2[i2 * 3 + 1], xi2v = xb2[i2 * 3 + 2];
            float a0 = xb2[tid * 3], a1 = xb2[tid * 3 + 1], a2 = xb2[tid * 3 + 2];
            float d0 = (a0 - xi0) + 1e-12f;
            float d1 = (a1 - xi1) + 1e-12f;
            float d2 = (a2 - xi2v) + 1e-12f;
            float dj = sqrtf(d0 * d0 + d1 * d1 + d2 * d2);
            uint4 row;
            row.x = cvt_f16x2(xi1, xi0);
            row.y = cvt_f16x2(a0, xi2v);
            row.z = cvt_f16x2(a2, a1);
            row.w = cvt_f16x2(1.0f, dj);
            *(uint4*)(sbytes + BAUG + tid * 32) = row;
        }
        if (tid < 3)
            sh[BYT / 2 + slot2 * 216 + 192 + tid] = __float2half(xb2[i2 * 3 + tid]);
    };

    auto mma0 = [&]() {   // h1 = lrelu(A_aug @ W1_aug), K=16 (bias folded)
        float acc[5][2][4];
        #pragma unroll
        for (int m = 0; m < 5; m++)
            #pragma unroll
            for (int j = 0; j < 2; j++)
                { acc[m][j][0]=0.f; acc[m][j][1]=0.f; acc[m][j][2]=0.f; acc[m][j][3]=0.f; }
        #pragma unroll
        for (int m = 0; m < 5; m++) {
            uint32_t a0, a1, a2, a3;
            LDSM_X4(a0, a1, a2, a3, aAugb + m * 512);
            #pragma unroll
            for (int j = 0; j < 2; j++)
                if (j < nt0) MMA16816(acc[m][j], a0, a1, a2, a3, bf1[j][0], bf1[j][1]);
        }
        #pragma unroll
        for (int m = 0; m < 5; m++) {
            #pragma unroll
            for (int j = 0; j < 2; j++)
                if (j < nt0) {
                    uint32_t p0 = cvt_f16x2(lrelu(acc[m][j][1]), lrelu(acc[m][j][0]));
                    uint32_t p1 = cvt_f16x2(lrelu(acc[m][j][3]), lrelu(acc[m][j][2]));
                    STSM_X2(h1stb + (uint32_t)(m * 16) * 208 + naug[j] * 2, p0, p1);
                }
        }
    };

    // ---- pipeline prologue: PhaseA + MMA0 for first bi ----
    int bi = blockIdx.x;
    int slot = 0;
    phaseA(bi, 0);
    __syncthreads();
    mma0();
    __syncthreads();

    // ---- steady state: 2 barriers per bi ----
    while (bi < 9600) {
        const int binext = bi + 148;
        const bool more = binext < 9600;

        // I1: PhaseA(next) + MMA1(cur): h2 = lrelu(h1 @ W2 + b2)
        if (more) phaseA(binext, slot + 1);
        {
            float acc[5][3][4];
            #pragma unroll
            for (int m = 0; m < 5; m++)
                #pragma unroll
                for (int j = 0; j < 3; j++)
                    { acc[m][j][0]=0.f; acc[m][j][1]=0.f; acc[m][j][2]=0.f; acc[m][j][3]=0.f; }
            #pragma unroll
            for (int k = 0; k < 6; k++) {
                #pragma unroll
                for (int m = 0; m < 5; m++) {
                    uint32_t a0, a1, a2, a3;
                    LDSM_X4(a0, a1, a2, a3, a1base + m * 3328 + k * 32);
                    #pragma unroll
                    for (int j = 0; j < 3; j++)
                        if (j < nt1) MMA16816(acc[m][j], a0, a1, a2, a3, bf2[k][j][0], bf2[k][j][1]);
                }
            }
            #pragma unroll
            for (int m = 0; m < 5; m++) {
                #pragma unroll
                for (int j = 0; j < 3; j++)
                    if (j < nt1) {
                        uint32_t p0 = cvt_f16x2(lrelu(acc[m][j][1] + e1b1[j]),
                                                lrelu(acc[m][j][0] + e1b0[j]));
                        uint32_t p1 = cvt_f16x2(lrelu(acc[m][j][3] + e1b1[j]),
                                                lrelu(acc[m][j][2] + e1b0[j]));
                        STSM_X2(h2stb + (uint32_t)(m * 16) * 336 + n1[j] * 2, p0, p1);
                    }
            }
        }
        __syncthreads();

        // I2: MMA0(next) -> h1 ; MMA2(cur): column sums -> y[slot]
        if (more) mma0();
        {
            float acc[5][3][4];
            #pragma unroll
            for (int m = 0; m < 5; m++)
                #pragma unroll
                for (int j = 0; j < 3; j++)
                    { acc[m][j][0]=0.f; acc[m][j][1]=0.f; acc[m][j][2]=0.f; acc[m][j][3]=0.f; }
            #pragma unroll
            for (int k = 0; k < 10; k++) {
                #pragma unroll
                for (int m = 0; m < 5; m++) {
                    uint32_t a0, a1, a2, a3;
                    LDSM_X4(a0, a1, a2, a3, a2base + m * 5376 + k * 32);
                    #pragma unroll
                    for (int j = 0; j < 3; j++)
                        MMA16816(acc[m][j], a0, a1, a2, a3, bf3[k][j][0], bf3[k][j][1]);
                }
            }
            float cs0[3] = {0.f, 0.f, 0.f}, cs1[3] = {0.f, 0.f, 0.f};
            #pragma unroll
            for (int m = 0; m < 5; m++) {
                bool ok2 = (m * 16 + 8 + qr) < 75;
                #pragma unroll
                for (int j = 0; j < 3; j++) {
                    cs0[j] += lrelu(acc[m][j][0] + e2b0[j]);
                    cs1[j] += lrelu(acc[m][j][1] + e2b1[j]);
                    if (ok2) {
                        cs0[j] += lrelu(acc[m][j][2] + e2b0[j]);
                        cs1[j] += lrelu(acc[m][j][3] + e2b1[j]);
                    }
                }
            }
            #pragma unroll
            for (int j = 0; j < 3; j++) {
                #pragma unroll
                for (int d = 4; d < 32; d <<= 1) {
                    cs0[j] += __shfl_xor_sync(0xFFFFFFFFu, cs0[j], d);
                    cs1[j] += __shfl_xor_sync(0xFFFFFFFFu, cs1[j], d);
                }
            }
            if (lane < 4) {
                #pragma unroll
                for (int j = 0; j < 3; j++)
                    s32[YTU + slot * 108 + n2[j] / 2 + lane] = cvt_f16x2(cs1[j], cs0[j]);
            }
        }
        __syncthreads();

        bi = binext;
        ++slot;
    }

    // ================= NODE TAIL =================
    const int nslots = (blockIdx.x < 128) ? 65 : 64;
    const int n0 = 32 * wid;
    const uint32_t aYbase  = sbase + BYT  + (uint32_t)(lA * 216 + gA * 8) * 2;
    const uint32_t aH1base = sbase + BH1T + (uint32_t)(lA * 264 + gA * 8) * 2;
    const uint32_t bWbase  = sbase + (uint32_t)(lB * 264) * 2;
    const uint32_t h1tstb  = sbase + BH1T + (uint32_t)(lane & 15) * 528;
    const uint32_t h2tstb  = sbase + (uint32_t)(lane & 15) * 528;

    for (int i = tid; i < 256; i += 256) s[OT_B1 + i] = nb1[i];
    for (int i = tid; i < 256; i += 256) s[OT_B2 + i] = nb2[i];
    for (int i = tid; i < 768; i += 256) s[OT_W3 + i] = nw3[i];
    if (tid < 3) s[OT_B3 + tid] = nb3[tid];
    {
        uint4* d = (uint4*)s32;
        for (int i = tid; i < 208 * 132 / 4; i += 256) d[i] = g_w1h[i];
    }
    __syncthreads();

    // ---- Tail phase 1 ----
    {
        float acc[5][4][4];
        #pragma unroll
        for (int m = 0; m < 5; m++)
            #pragma unroll
            for (int j = 0; j < 4; j++)
                { acc[m][j][0]=0.f; acc[m][j][1]=0.f; acc[m][j][2]=0.f; acc[m][j][3]=0.f; }
        #pragma unroll
        for (int kc = 0; kc < 13; kc++) {
            uint32_t bf[4][2];
            #pragma unroll
            for (int j = 0; j < 4; j++)
                LDSM_X2T(bf[j][0], bf[j][1], bWbase + kc * 8448 + (n0 + 8 * j) * 2);
            #pragma unroll
            for (int m = 0; m < 5; m++) {
                uint32_t a0, a1, a2, a3;
                LDSM_X4(a0, a1, a2, a3, aYbase + m * 6912 + kc * 32);
                #pragma unroll
                for (int j = 0; j < 4; j++)
                    MMA16816(acc[m][j], a0, a1, a2, a3, bf[j][0], bf[j][1]);
            }
        }
        #pragma unroll
        for (int m = 0; m < 5; m++) {
            #pragma unroll
            for (int j = 0; j < 4; j++) {
                float bb0 = s[OT_B1 + n0 + 8 * j + 2 * qc];
                float bb1 = s[OT_B1 + n0 + 8 * j + 2 * qc + 1];
                uint32_t p0 = cvt_f16x2(lrelu(acc[m][j][1] + bb1), lrelu(acc[m][j][0] + bb0));
                uint32_t p1 = cvt_f16x2(lrelu(acc[m][j][3] + bb1), lrelu(acc[m][j][2] + bb0));
                STSM_X2(h1tstb + (uint32_t)(m * 16) * 528 + (n0 + 8 * j) * 2, p0, p1);
            }
        }
    }
    __syncthreads();

    {
        uint4* d = (uint4*)s32;
        for (int i = tid; i < 256 * 132 / 4; i += 256) d[i] = g_w2h[i];
    }
    __syncthreads();

    // ---- Tail phase 2 ----
    {
        float acc[5][4][4];
        #pragma unroll
        for (int m = 0; m < 5; m++)
            #pragma unroll
            for (int j = 0; j < 4; j++)
                { acc[m][j][0]=0.f; acc[m][j][1]=0.f; acc[m][j][2]=0.f; acc[m][j][3]=0.f; }
        #pragma unroll
        for (int kc = 0; kc < 16; kc++) {
            uint32_t bf[4][2];
            #pragma unroll
            for (int j = 0; j < 4; j++)
                LDSM_X2T(bf[j][0], bf[j][1], bWbase + kc * 8448 + (n0 + 8 * j) * 2);
            #pragma unroll
            for (int m = 0; m < 5; m++) {
                uint32_t a0, a1, a2, a3;
                LDSM_X4(a0, a1, a2, a3, aH1base + m * 8448 + kc * 32);
                #pragma unroll
                for (int j = 0; j < 4; j++)
                    MMA16816(acc[m][j], a0, a1, a2, a3, bf[j][0], bf[j][1]);
            }
        }
        __syncthreads();
        #pragma unroll
        for (int m = 0; m < 5; m++) {
            #pragma unroll
            for (int j = 0; j < 4; j++) {
                float bb0 = s[OT_B2 + n0 + 8 * j + 2 * qc];
                float bb1 = s[OT_B2 + n0 + 8 * j + 2 * qc + 1];
                uint32_t p0 = cvt_f16x2(lrelu(acc[m][j][1] + bb1), lrelu(acc[m][j][0] + bb0));
                uint32_t p1 = cvt_f16x2(lrelu(acc[m][j][3] + bb1), lrelu(acc[m][j][2] + bb0));
                STSM_X2(h2tstb + (uint32_t)(m * 16) * 528 + (n0 + 8 * j) * 2, p0, p1);
            }
        }
    }
    __syncthreads();

    // ---- Tail phase 3 ----
    if (tid < 240) {
        int r = tid / 3, o = tid - r * 3;
        if (r < nslots) {
            const __half2* hr = (const __half2*)(sh + r * 264);
            float a = s[OT_B3 + o];
            #pragma unroll 8
            for (int k2 = 0; k2 < 128; k2++) {
                float2 h = __half22float2(hr[k2]);
                a += h.x * s[OT_W3 + 6 * k2 + o] + h.y * s[OT_W3 + 6 * k2 + 3 + o];
            }
            out[(blockIdx.x + r * 148) * 3 + o] = a;
        }
    }
}

extern "C" void kernel_launch(void* const* d_in, const int* in_sizes, int n_in,
                              void* d_out, int out_size)
{
    const float* x    = (const float*)d_in[0];
    const float* few1 = (const float*)d_in[1];
    const float* feb1 = (const float*)d_in[2];
    const float* few2 = (const float*)d_in[3];
    const float* feb2 = (const float*)d_in[4];
    const float* few3 = (const float*)d_in[5];
    const float* feb3 = (const float*)d_in[6];
    const float* fnw1 = (const float*)d_in[7];
    const float* fnb1 = (const float*)d_in[8];
    const float* fnw2 = (const float*)d_in[9];
    const float* fnb2 = (const float*)d_in[10];
    const float* fnw3 = (const float*)d_in[11];
    const float* fnb3 = (const float*)d_in[12];
    float* out = (float*)d_out;

    cudaFuncSetAttribute(edge_kernel, cudaFuncAttributeMaxDynamicSharedMemorySize, SMEM1_BYTES);

    prep_kernel<<<132, 256>>>(fnw1, fnw2);
    edge_kernel<<<148, 256, SMEM1_BYTES>>>(x, few1, feb1, few2, feb2, few3, feb3,
                                           fnb1, fnb2, fnw3, fnb3, out);
}